// round 3
// baseline (speedup 1.0000x reference)
#include <cuda_runtime.h>
#include <math.h>

#define N_NODES 100000
#define N_EDGES 1600000

// ---------------- device scratch (no allocations allowed) ----------------
__device__ float g_hA [N_NODES * 32];
__device__ float g_hB [N_NODES * 64];
__device__ float g_m  [N_NODES * 64];
__device__ float g_agg[N_NODES * 64];
__device__ float g_gi [N_NODES * 192];
__device__ float g_gh [N_NODES * 192];
__device__ float g_hid[N_NODES * 128];
__device__ float g_WT1ih[32 * 96];
__device__ float g_WT1hh[32 * 96];
__device__ float g_WT2ih[64 * 192];
__device__ float g_WT2hh[64 * 192];
__device__ float g_fc1T[64 * 128];
__device__ float g_fc2T[128 * 10];
__device__ int   g_ei32[2 * N_EDGES];
__device__ int   g_deg [N_NODES];
__device__ int   g_rowptr[N_NODES + 1];
__device__ int   g_cursor[N_NODES];
__device__ int   g_esrc[N_EDGES];
__device__ float g_ews [N_EDGES];
__device__ int   g_is64;

// ---------------- helpers ----------------
__device__ __forceinline__ float sigmoidf_(float x) { return 1.0f / (1.0f + expf(-x)); }
__device__ __forceinline__ float eluf_(float x)     { return x > 0.f ? x : expm1f(x); }

// ---------------- edge-index dtype sniff + normalize ----------------
__global__ void k_sniff(const void* __restrict__ p) {
    __shared__ int s_bad;
    if (threadIdx.x == 0) s_bad = 0;
    __syncthreads();
    long long v = ((const long long*)p)[threadIdx.x];   // 1024 threads
    if (v < 0 || v >= N_NODES) atomicAdd(&s_bad, 1);
    __syncthreads();
    if (threadIdx.x == 0) g_is64 = (s_bad < 512) ? 1 : 0;
}

__global__ void k_convert(const void* __restrict__ p, int* __restrict__ out) {
    int i = blockIdx.x * blockDim.x + threadIdx.x;
    if (i >= 2 * N_EDGES) return;
    out[i] = g_is64 ? (int)((const long long*)p)[i] : ((const int*)p)[i];
}

// ---------------- CSR build ----------------
__global__ void k_zero_i(int* __restrict__ p, int n) {
    int i = blockIdx.x * blockDim.x + threadIdx.x;
    if (i < n) p[i] = 0;
}

__global__ void k_count(const int* __restrict__ ei, int* __restrict__ deg) {
    int e = blockIdx.x * blockDim.x + threadIdx.x;
    if (e >= N_EDGES) return;
    int d = ei[N_EDGES + e];
    if ((unsigned)d < N_NODES) atomicAdd(&deg[d], 1);
}

__global__ void k_scan(const int* __restrict__ deg, int* __restrict__ rowptr) {
    __shared__ int s[1024];
    __shared__ int s_off;
    int tid = threadIdx.x;
    if (tid == 0) s_off = 0;
    for (int base = 0; base < N_NODES; base += 1024) {
        int i = base + tid;
        int v = (i < N_NODES) ? deg[i] : 0;
        __syncthreads();
        s[tid] = v;
        __syncthreads();
        for (int d = 1; d < 1024; d <<= 1) {
            int t = (tid >= d) ? s[tid - d] : 0;
            __syncthreads();
            s[tid] += t;
            __syncthreads();
        }
        if (i < N_NODES) rowptr[i] = s_off + s[tid] - v;
        int total = s[1023];
        __syncthreads();
        if (tid == 0) s_off += total;
    }
    __syncthreads();
    if (tid == 0) rowptr[N_NODES] = s_off;
}

__global__ void k_copy_i(const int* __restrict__ a, int* __restrict__ b, int n) {
    int i = blockIdx.x * blockDim.x + threadIdx.x;
    if (i < n) b[i] = a[i];
}

__global__ void k_place(const int* __restrict__ ei, const float* __restrict__ ea,
                        int* __restrict__ cursor, int* __restrict__ esrc,
                        float* __restrict__ ews) {
    int e = blockIdx.x * blockDim.x + threadIdx.x;
    if (e >= N_EDGES) return;
    int s = ei[e];
    int d = ei[N_EDGES + e];
    if ((unsigned)s >= N_NODES || (unsigned)d >= N_NODES) return;
    int pos = atomicAdd(&cursor[d], 1);
    esrc[pos] = s;
    ews[pos]  = ea[e];
}

// ---------------- init / misc elementwise ----------------
__global__ void k_transpose(const float* __restrict__ W, float* __restrict__ WT, int R, int K) {
    int idx = blockIdx.x * blockDim.x + threadIdx.x;
    if (idx < R * K) { int r = idx / K, k = idx - r * K; WT[k * R + r] = W[idx]; }
}

__global__ void k_init_h(const float* __restrict__ x, float* __restrict__ h) {
    int i = blockIdx.x * blockDim.x + threadIdx.x;
    if (i < N_NODES * 32) {
        int n = i >> 5, c = i & 31;
        h[i] = (c < 16) ? x[n * 16 + c] : 0.f;
    }
}

__global__ void k_pad_elu(const float* __restrict__ src, float* __restrict__ dst) {
    int i = blockIdx.x * blockDim.x + threadIdx.x;
    if (i < N_NODES * 64) {
        int n = i >> 6, c = i & 63;
        dst[i] = (c < 32) ? eluf_(src[n * 32 + c]) : 0.f;
    }
}

__global__ void k_elu(float* __restrict__ p, int n) {
    int i = blockIdx.x * blockDim.x + threadIdx.x;
    if (i < n) p[i] = eluf_(p[i]);
}

// ---------------- tiled GEMM: Y[N,R] = act(X[N,K] @ WT[K,R] + bias) ----------------
// WT is k-major. Tile: 64 nodes x RT cols, 4x4 micro-tile, (RT/4)*16 threads.
template <int K, int RT>
__global__ void k_gemm_t(const float* __restrict__ X, const float* __restrict__ WT,
                         const float* __restrict__ bias, float* __restrict__ Y,
                         int N, int R, int act) {
    const int NT = 64;
    __shared__ float sX[NT][K];
    __shared__ float sW[K][RT];
    int n0 = blockIdx.x * NT;
    int r0 = blockIdx.y * RT;
    int tid = threadIdx.x;

    for (int i = tid; i < NT * K; i += blockDim.x) {
        int n = i / K, k = i - n * K;
        int nn = n0 + n;
        sX[n][k] = (nn < N) ? X[(size_t)nn * K + k] : 0.f;
    }
    for (int i = tid; i < K * RT; i += blockDim.x) {
        int k = i / RT, r = i - k * RT;
        sW[k][r] = WT[(size_t)k * R + r0 + r];
    }
    __syncthreads();

    int tc = tid % (RT / 4);
    int tn = tid / (RT / 4);
    float acc[4][4];
#pragma unroll
    for (int i = 0; i < 4; i++)
#pragma unroll
        for (int j = 0; j < 4; j++) acc[i][j] = 0.f;

#pragma unroll
    for (int k = 0; k < K; k++) {
        float a0 = sX[tn * 4 + 0][k];
        float a1 = sX[tn * 4 + 1][k];
        float a2 = sX[tn * 4 + 2][k];
        float a3 = sX[tn * 4 + 3][k];
        float4 b = *(const float4*)&sW[k][tc * 4];
        acc[0][0] = fmaf(a0, b.x, acc[0][0]); acc[0][1] = fmaf(a0, b.y, acc[0][1]);
        acc[0][2] = fmaf(a0, b.z, acc[0][2]); acc[0][3] = fmaf(a0, b.w, acc[0][3]);
        acc[1][0] = fmaf(a1, b.x, acc[1][0]); acc[1][1] = fmaf(a1, b.y, acc[1][1]);
        acc[1][2] = fmaf(a1, b.z, acc[1][2]); acc[1][3] = fmaf(a1, b.w, acc[1][3]);
        acc[2][0] = fmaf(a2, b.x, acc[2][0]); acc[2][1] = fmaf(a2, b.y, acc[2][1]);
        acc[2][2] = fmaf(a2, b.z, acc[2][2]); acc[2][3] = fmaf(a2, b.w, acc[2][3]);
        acc[3][0] = fmaf(a3, b.x, acc[3][0]); acc[3][1] = fmaf(a3, b.y, acc[3][1]);
        acc[3][2] = fmaf(a3, b.z, acc[3][2]); acc[3][3] = fmaf(a3, b.w, acc[3][3]);
    }

    float bv[4] = {0.f, 0.f, 0.f, 0.f};
    if (bias) {
#pragma unroll
        for (int j = 0; j < 4; j++) bv[j] = bias[r0 + tc * 4 + j];
    }
#pragma unroll
    for (int i = 0; i < 4; i++) {
        int nn = n0 + tn * 4 + i;
        if (nn >= N) continue;
        float4 o;
        o.x = acc[i][0] + bv[0]; o.y = acc[i][1] + bv[1];
        o.z = acc[i][2] + bv[2]; o.w = acc[i][3] + bv[3];
        if (act) { o.x = eluf_(o.x); o.y = eluf_(o.y); o.z = eluf_(o.z); o.w = eluf_(o.w); }
        *(float4*)&Y[(size_t)nn * R + r0 + tc * 4] = o;
    }
}

// ---------------- CSR gather-max (replaces atomic scatter) ----------------
template <int C>
__global__ void k_gather(const float* __restrict__ m, const int* __restrict__ rowptr,
                         const int* __restrict__ esrc, const float* __restrict__ ews,
                         float* __restrict__ agg) {
    const int NPB = 256 / C;
    int c = threadIdx.x;
    int n = blockIdx.x * NPB + threadIdx.y;
    if (n >= N_NODES) return;
    int beg = rowptr[n], end = rowptr[n + 1];
    float acc = -INFINITY;
    for (int e = beg; e < end; e++) {
        int s   = esrc[e];          // broadcast across the warp
        float w = ews[e];
        acc = fmaxf(acc, m[(size_t)s * C + c] * w);
    }
    agg[(size_t)n * C + c] = isfinite(acc) ? acc : 0.f;   // empty segment -> 0
}

// ---------------- GRU elementwise combine ----------------
template <int C>
__global__ void k_gru_comb(const float* __restrict__ gi, const float* __restrict__ gh,
                           float* __restrict__ h) {
    int i = blockIdx.x * blockDim.x + threadIdx.x;
    if (i >= N_NODES * C) return;
    int n = i / C, c = i - n * C;
    const float* gin = gi + (size_t)n * 3 * C;
    const float* ghn = gh + (size_t)n * 3 * C;
    float r  = sigmoidf_(gin[c]         + ghn[c]);
    float z  = sigmoidf_(gin[C + c]     + ghn[C + c]);
    float nn = tanhf    (gin[2 * C + c] + r * ghn[2 * C + c]);
    float hv = h[i];
    h[i] = (1.f - z) * nn + z * hv;
}

// ---------------- fc2 + log_softmax ----------------
__global__ void k_fc2_lsm(const float* __restrict__ X, const float* __restrict__ Wt,
                          const float* __restrict__ b, float* __restrict__ out) {
    int gt   = blockIdx.x * blockDim.x + threadIdx.x;
    int node = gt >> 5, lane = gt & 31;
    if (node >= N_NODES) return;
    const float* xr = X + (size_t)node * 128;
    float acc[10];
#pragma unroll
    for (int j = 0; j < 10; j++) acc[j] = 0.f;
    for (int k = lane; k < 128; k += 32) {
        float xv = xr[k];
        const float* w = Wt + k * 10;
#pragma unroll
        for (int j = 0; j < 10; j++) acc[j] = fmaf(xv, w[j], acc[j]);
    }
#pragma unroll
    for (int j = 0; j < 10; j++)
        for (int off = 16; off; off >>= 1) acc[j] += __shfl_xor_sync(0xffffffffu, acc[j], off);
    float mx = -INFINITY;
#pragma unroll
    for (int j = 0; j < 10; j++) { acc[j] += b[j]; mx = fmaxf(mx, acc[j]); }
    float se = 0.f;
#pragma unroll
    for (int j = 0; j < 10; j++) se += expf(acc[j] - mx);
    float lse = mx + logf(se);
    if (lane < 10) out[(size_t)node * 10 + lane] = acc[lane] - lse;
}

// ---------------- launch ----------------
static inline int gdiv(int n) { return (n + 255) / 256; }

extern "C" void kernel_launch(void* const* d_in, const int* in_sizes, int n_in,
                              void* d_out, int out_size) {
    const float* x    = (const float*)d_in[0];
    const void*  eraw = d_in[1];
    const float* ea   = (const float*)d_in[2];
    const float* W1   = (const float*)d_in[3];
    const float* Wih1 = (const float*)d_in[4];
    const float* Whh1 = (const float*)d_in[5];
    const float* bih1 = (const float*)d_in[6];
    const float* bhh1 = (const float*)d_in[7];
    const float* W2   = (const float*)d_in[8];
    const float* Wih2 = (const float*)d_in[9];
    const float* Whh2 = (const float*)d_in[10];
    const float* bih2 = (const float*)d_in[11];
    const float* bhh2 = (const float*)d_in[12];
    const float* fc1w = (const float*)d_in[13];
    const float* fc1b = (const float*)d_in[14];
    const float* fc2w = (const float*)d_in[15];
    const float* fc2b = (const float*)d_in[16];
    float* out = (float*)d_out;

    float *hA, *hB, *m, *agg, *gi, *gh, *hid;
    float *WT1ih, *WT1hh, *WT2ih, *WT2hh, *fc1T, *fc2T, *ews;
    int *ei32, *deg, *rowptr, *cursor, *esrc;
    cudaGetSymbolAddress((void**)&hA,    g_hA);
    cudaGetSymbolAddress((void**)&hB,    g_hB);
    cudaGetSymbolAddress((void**)&m,     g_m);
    cudaGetSymbolAddress((void**)&agg,   g_agg);
    cudaGetSymbolAddress((void**)&gi,    g_gi);
    cudaGetSymbolAddress((void**)&gh,    g_gh);
    cudaGetSymbolAddress((void**)&hid,   g_hid);
    cudaGetSymbolAddress((void**)&WT1ih, g_WT1ih);
    cudaGetSymbolAddress((void**)&WT1hh, g_WT1hh);
    cudaGetSymbolAddress((void**)&WT2ih, g_WT2ih);
    cudaGetSymbolAddress((void**)&WT2hh, g_WT2hh);
    cudaGetSymbolAddress((void**)&fc1T,  g_fc1T);
    cudaGetSymbolAddress((void**)&fc2T,  g_fc2T);
    cudaGetSymbolAddress((void**)&ei32,  g_ei32);
    cudaGetSymbolAddress((void**)&deg,   g_deg);
    cudaGetSymbolAddress((void**)&rowptr,g_rowptr);
    cudaGetSymbolAddress((void**)&cursor,g_cursor);
    cudaGetSymbolAddress((void**)&esrc,  g_esrc);
    cudaGetSymbolAddress((void**)&ews,   g_ews);

    const int TB = 256;

    // edge indices -> int32, then CSR by destination
    k_sniff<<<1, 1024>>>(eraw);
    k_convert<<<gdiv(2 * N_EDGES), TB>>>(eraw, ei32);
    k_zero_i<<<gdiv(N_NODES), TB>>>(deg, N_NODES);
    k_count<<<gdiv(N_EDGES), TB>>>(ei32, deg);
    k_scan<<<1, 1024>>>(deg, rowptr);
    k_copy_i<<<gdiv(N_NODES), TB>>>(rowptr, cursor, N_NODES);
    k_place<<<gdiv(N_EDGES), TB>>>(ei32, ea, cursor, esrc, ews);

    // weight transposes (k-major)
    k_transpose<<<gdiv(96 * 32),  TB>>>(Wih1, WT1ih, 96,  32);
    k_transpose<<<gdiv(96 * 32),  TB>>>(Whh1, WT1hh, 96,  32);
    k_transpose<<<gdiv(192 * 64), TB>>>(Wih2, WT2ih, 192, 64);
    k_transpose<<<gdiv(192 * 64), TB>>>(Whh2, WT2hh, 192, 64);
    k_transpose<<<gdiv(128 * 64), TB>>>(fc1w, fc1T,  128, 64);
    k_transpose<<<gdiv(10 * 128), TB>>>(fc2w, fc2T,  10,  128);

    // ---- layer 1 (C=32) ----
    k_init_h<<<gdiv(N_NODES * 32), TB>>>(x, hA);
    for (int i = 0; i < 3; i++) {
        // m = h @ W1[i]   (W1[i] is already k-major [32][32])
        k_gemm_t<32, 32><<<dim3((N_NODES + 63) / 64, 1), 128>>>(hA, W1 + i * 32 * 32, nullptr, m, N_NODES, 32, 0);
        { dim3 blk(32, 8); k_gather<32><<<(N_NODES + 7) / 8, blk>>>(m, rowptr, esrc, ews, agg); }
        k_gemm_t<32, 32><<<dim3((N_NODES + 63) / 64, 3), 128>>>(agg, WT1ih, bih1, gi, N_NODES, 96, 0);
        k_gemm_t<32, 32><<<dim3((N_NODES + 63) / 64, 3), 128>>>(hA,  WT1hh, bhh1, gh, N_NODES, 96, 0);
        k_gru_comb<32><<<gdiv(N_NODES * 32), TB>>>(gi, gh, hA);
    }

    k_pad_elu<<<gdiv(N_NODES * 64), TB>>>(hA, hB);

    // ---- layer 2 (C=64) ----
    for (int i = 0; i < 3; i++) {
        k_gemm_t<64, 64><<<dim3((N_NODES + 63) / 64, 1), 256>>>(hB, W2 + i * 64 * 64, nullptr, m, N_NODES, 64, 0);
        { dim3 blk(64, 4); k_gather<64><<<(N_NODES + 3) / 4, blk>>>(m, rowptr, esrc, ews, agg); }
        k_gemm_t<64, 64><<<dim3((N_NODES + 63) / 64, 3), 256>>>(agg, WT2ih, bih2, gi, N_NODES, 192, 0);
        k_gemm_t<64, 64><<<dim3((N_NODES + 63) / 64, 3), 256>>>(hB,  WT2hh, bhh2, gh, N_NODES, 192, 0);
        k_gru_comb<64><<<gdiv(N_NODES * 64), TB>>>(gi, gh, hB);
    }

    // ---- head ----
    k_elu<<<gdiv(N_NODES * 64), TB>>>(hB, N_NODES * 64);
    k_gemm_t<64, 64><<<dim3((N_NODES + 63) / 64, 2), 256>>>(hB, fc1T, fc1b, hid, N_NODES, 128, 1);
    k_fc2_lsm<<<gdiv(N_NODES * 32), TB>>>(hid, fc2T, fc2b, out);
}